// round 14
// baseline (speedup 1.0000x reference)
#include <cuda_runtime.h>
#include <cuda_fp16.h>
#include <cstdint>
#include <cstddef>

// Problem constants (fixed by dataset)
#define T_TOT 131072
#define CDIM  512
#define NF    1024   // interleaved [y_0,z_0,y_1,z_1,...]  (y=W1 path, z=W2W1 path)
#define BATCH 128

// tcgen05 requires the sm_103a ("arch-accelerated") target pass.
#if defined(__CUDA_ARCH_FEAT_SM103_ALL)
#define HAS_TC 1
#else
#define HAS_TC 0
#endif

// ---------------- scratch: __device__ globals (no allocation allowed) ----------------
// Tiled + pre-swizzled layouts (32 KB blocks = smem images for cp.async.bulk):
// A block (row-tile R of 256 rows, K-chunk c): base=(R*8+c)*32768, two 16 KB
//   sub-halves of 128 rows each -> a 128-row CTA uses one 16 KB half directly.
// B block (icol-tile nt of 256, K-chunk c): base=(nt*8+c)*32768.
__device__ __half g_x[(size_t)T_TOT * CDIM];     // LN output fp16, tiled    134 MB
__device__ __half g_wcat[(size_t)NF * CDIM];     // interleaved weights, tiled (1 MB)
__device__ float  g_bcat[NF];                    // interleaved [b1_d ; (W2 b1 + b2)_d]
__device__ float  g_num[BATCH * CDIM];           // Σ w*y per (graph, d)
__device__ float  g_den[BATCH * CDIM];           // Σ w   per (graph, d)

// ---------------- PTX helpers ----------------
__device__ __forceinline__ uint32_t smem_u32(const void* p) {
    return (uint32_t)__cvta_generic_to_shared(p);
}
#define SWZ128(o) ((o) ^ (((o) >> 3) & 0x70))

// ---------------- K1a: W1 row d -> wcat icol 2d (fp16, tiled); zero accumulators ----
__global__ void k_wcopy(const float* __restrict__ W1) {
    int i = blockIdx.x * 256 + threadIdx.x;      // 262144 elements
    int d = i >> 9, k = i & 511;
    int icol = 2 * d;
    int nt = icol >> 8, rloc = icol & 255;
    int c = k >> 6, klocb = (k & 63) * 2;
    size_t base = ((size_t)(nt * 8 + c)) * 32768;
    uint32_t off = SWZ128((uint32_t)(rloc * 128 + klocb));
    *(__half*)((char*)g_wcat + base + off) = __float2half(W1[i]);
    if (i < BATCH * CDIM) { g_num[i] = 0.f; g_den[i] = 0.f; }
}

// ---------------- K1b: bcat interleaved [b1_d ; (W2@b1+b2)_d], warp-per-output ------
__global__ void k_bcat(const float* __restrict__ W2, const float* __restrict__ b1,
                       const float* __restrict__ b2) {
    int w = (blockIdx.x * 256 + threadIdx.x) >> 5;   // 0..511 (grid 64 x 256)
    int lane = threadIdx.x & 31;
    float acc = 0.f;
    const float* row = W2 + (size_t)w * CDIM;
#pragma unroll 4
    for (int j = lane; j < CDIM; j += 32) acc += row[j] * __ldg(&b1[j]);
#pragma unroll
    for (int o = 16; o > 0; o >>= 1) acc += __shfl_xor_sync(0xFFFFFFFFu, acc, o);
    if (lane == 0) {
        g_bcat[2 * w]     = __ldg(&b1[w]);
        g_bcat[2 * w + 1] = acc + __ldg(&b2[w]);
    }
}

// ---------------- K1c: W21 = W2 @ W1 -> wcat icol 2d+1 (fp16, tiled) ----------------
__global__ void __launch_bounds__(256) k_w21(const float* __restrict__ W2,
                                             const float* __restrict__ W1) {
    __shared__ float sA[32][65];
    __shared__ float sB[32][64];
    int t = threadIdx.x;
    int tx = t & 15, ty = t >> 4;
    int d0 = blockIdx.y * 64, k0 = blockIdx.x * 64;
    float acc[4][4] = {};
    for (int jc = 0; jc < CDIM; jc += 32) {
        for (int i = t; i < 64 * 32; i += 256) {
            int r = i >> 5, j = i & 31;
            sA[j][r] = W2[(size_t)(d0 + r) * CDIM + jc + j];
        }
        for (int i = t; i < 32 * 64; i += 256) {
            int j = i >> 6, c = i & 63;
            sB[j][c] = W1[(size_t)(jc + j) * CDIM + k0 + c];
        }
        __syncthreads();
#pragma unroll
        for (int j = 0; j < 32; j++) {
            float a[4], b[4];
#pragma unroll
            for (int i = 0; i < 4; i++) a[i] = sA[j][ty * 4 + i];
#pragma unroll
            for (int l = 0; l < 4; l++) b[l] = sB[j][tx * 4 + l];
#pragma unroll
            for (int i = 0; i < 4; i++)
#pragma unroll
                for (int l = 0; l < 4; l++) acc[i][l] += a[i] * b[l];
        }
        __syncthreads();
    }
#pragma unroll
    for (int i = 0; i < 4; i++)
#pragma unroll
        for (int l = 0; l < 4; l++) {
            int dr = d0 + ty * 4 + i;
            int k  = k0 + tx * 4 + l;
            int icol = 2 * dr + 1;
            int nt = icol >> 8, rloc = icol & 255;
            int c = k >> 6, klocb = (k & 63) * 2;
            size_t base = ((size_t)(nt * 8 + c)) * 32768;
            uint32_t off = SWZ128((uint32_t)(rloc * 128 + klocb));
            *(__half*)((char*)g_wcat + base + off) = __float2half(acc[i][l]);
        }
}

// ---------------- K2: LayerNorm (eps=1e-5), WARP-PER-ROW -> fp16 tiled+swizzled -----
// 256 threads = 8 rows/block; lane owns 16 cols; pure-shfl reduction (no smem,
// no __syncthreads); 4 independent float4 loads per lane for deep MLP.
__global__ void __launch_bounds__(256) k_ln(const float* __restrict__ hs,
                                            const float* __restrict__ gamma,
                                            const float* __restrict__ beta) {
    const int wid = threadIdx.x >> 5;
    const int lane = threadIdx.x & 31;
    const int row = blockIdx.x * 8 + wid;
    const float4* src = (const float4*)(hs + (size_t)row * CDIM) + lane * 4;
    float4 v0 = __ldg(src + 0);
    float4 v1 = __ldg(src + 1);
    float4 v2 = __ldg(src + 2);
    float4 v3 = __ldg(src + 3);
    float s = (v0.x + v0.y + v0.z + v0.w) + (v1.x + v1.y + v1.z + v1.w)
            + (v2.x + v2.y + v2.z + v2.w) + (v3.x + v3.y + v3.z + v3.w);
    float q = (v0.x * v0.x + v0.y * v0.y + v0.z * v0.z + v0.w * v0.w)
            + (v1.x * v1.x + v1.y * v1.y + v1.z * v1.z + v1.w * v1.w)
            + (v2.x * v2.x + v2.y * v2.y + v2.z * v2.z + v2.w * v2.w)
            + (v3.x * v3.x + v3.y * v3.y + v3.z * v3.z + v3.w * v3.w);
#pragma unroll
    for (int o = 16; o > 0; o >>= 1) {
        s += __shfl_xor_sync(0xFFFFFFFFu, s, o);
        q += __shfl_xor_sync(0xFFFFFFFFu, q, o);
    }
    const float mu = s * (1.f / CDIM);
    const float var = q * (1.f / CDIM) - mu * mu;
    const float rs = rsqrtf(var + 1e-5f);
    const float4* gsrc = (const float4*)gamma + lane * 4;
    const float4* bsrc = (const float4*)beta + lane * 4;
    float4 g0 = __ldg(gsrc + 0), g1 = __ldg(gsrc + 1), g2 = __ldg(gsrc + 2), g3 = __ldg(gsrc + 3);
    float4 b0 = __ldg(bsrc + 0), b1 = __ldg(bsrc + 1), b2 = __ldg(bsrc + 2), b3 = __ldg(bsrc + 3);
    uint4 o0, o1;
    {
        __half2 h0 = __floats2half2_rn((v0.x - mu) * rs * g0.x + b0.x, (v0.y - mu) * rs * g0.y + b0.y);
        __half2 h1 = __floats2half2_rn((v0.z - mu) * rs * g0.z + b0.z, (v0.w - mu) * rs * g0.w + b0.w);
        __half2 h2 = __floats2half2_rn((v1.x - mu) * rs * g1.x + b1.x, (v1.y - mu) * rs * g1.y + b1.y);
        __half2 h3 = __floats2half2_rn((v1.z - mu) * rs * g1.z + b1.z, (v1.w - mu) * rs * g1.w + b1.w);
        o0.x = *(uint32_t*)&h0; o0.y = *(uint32_t*)&h1;
        o0.z = *(uint32_t*)&h2; o0.w = *(uint32_t*)&h3;
        __half2 h4 = __floats2half2_rn((v2.x - mu) * rs * g2.x + b2.x, (v2.y - mu) * rs * g2.y + b2.y);
        __half2 h5 = __floats2half2_rn((v2.z - mu) * rs * g2.z + b2.z, (v2.w - mu) * rs * g2.w + b2.w);
        __half2 h6 = __floats2half2_rn((v3.x - mu) * rs * g3.x + b3.x, (v3.y - mu) * rs * g3.y + b3.y);
        __half2 h7 = __floats2half2_rn((v3.z - mu) * rs * g3.z + b3.z, (v3.w - mu) * rs * g3.w + b3.w);
        o1.x = *(uint32_t*)&h4; o1.y = *(uint32_t*)&h5;
        o1.z = *(uint32_t*)&h6; o1.w = *(uint32_t*)&h7;
    }
    // tiled + pre-swizzled destination (same mapping as before, audited)
    const int R = row >> 8, sub = (row >> 7) & 1, rloc = row & 127;
#pragma unroll
    for (int j = 0; j < 2; j++) {
        const int k = lane * 16 + j * 8;           // first col of this 8-half group
        const int c = k >> 6;
        const int klocb = (k & 63) * 2;
        size_t base = ((size_t)(R * 8 + c)) * 32768 + (size_t)sub * 16384;
        uint32_t off = SWZ128((uint32_t)(rloc * 128 + klocb));
        *(uint4*)((char*)g_x + base + off) = j ? o1 : o0;
    }
}

// ============================================================================
// K3: tcgen05 GEMM + fused softmax-pool epilogue (sm_103a pass only)
// CTA tile M=128 x N=256 icols; grid (4 nt, 1024 Rt128); TMEM 256 cols/CTA,
// 2 CTAs/SM. 2-stage bulk-copy pipeline (warp 0), mbarrier full/empty.
// [verbatim from the 303.3 us R7 kernel]
// ============================================================================
#define STG_BYTES 49152           // A 16K | B 32K
#define SM_CTRL   2048
#define SM_TOTAL_TC (SM_CTRL + 2 * STG_BYTES)   // 100352
#define IDESC 0x8400010u          // f16*f16->f32, M=128, N=256

#if HAS_TC
__device__ __forceinline__ uint32_t elect_one_pred() {
    uint32_t pred;
    asm volatile("{\n\t.reg .pred p;\n\telect.sync _|p, 0xFFFFFFFF;\n\tselp.b32 %0, 1, 0, p;\n\t}"
                 : "=r"(pred));
    return pred;
}
static constexpr uint64_t SMEM_DESC_BASE_SW128 =
    (uint64_t(2) << 61) | (uint64_t(1) << 46) | (uint64_t(64) << 32) | (uint64_t(1) << 16);
#define MAKE_SMEM_DESC(b) (SMEM_DESC_BASE_SW128 | ((uint64_t)((b) >> 4) & 0x3FFF))
#define MBARRIER_INIT(a, c) \
    asm volatile("mbarrier.init.shared.b64 [%0], %1;" :: "r"(a), "r"(c) : "memory")
#define MBAR_EXPECT_TX(a, n) \
    asm volatile("mbarrier.arrive.expect_tx.shared.b64 _, [%0], %1;" :: "r"(a), "r"(n) : "memory")
#define MBAR_WAIT(a, ph) do {                                                  \
    asm volatile("{\n\t.reg .pred P1;\n\t"                                     \
        "WL_%=:\n\t"                                                           \
        "mbarrier.try_wait.parity.acquire.cta.shared::cta.b64 P1, [%0], %1, 0x989680;\n\t" \
        "@P1 bra.uni WD_%=;\n\t"                                               \
        "bra.uni WL_%=;\n\t"                                                   \
        "WD_%=:\n\t}" :: "r"(a), "r"(ph) : "memory");                          \
} while (0)
#define BULK_CP(dst, src, n, mbar) \
    asm volatile("cp.async.bulk.shared::cta.global.mbarrier::complete_tx::bytes " \
                 "[%0], [%1], %2, [%3];" \
                 :: "r"(dst), "l"(src), "r"(n), "r"(mbar) : "memory")
__device__ __forceinline__ void mma_f16_ss(uint32_t d_tmem, uint64_t a_desc, uint64_t b_desc,
                                           uint32_t idesc, uint32_t en) {
    uint32_t z = 0;
    asm volatile(
        "{\n\t.reg .pred p;\n\t"
        "setp.ne.u32 p, %5, 0;\n\t"
        "tcgen05.mma.cta_group::1.kind::f16 [%0], %1, %2, %3, {%4, %4, %4, %4}, p;\n\t"
        "}"
        :: "r"(d_tmem), "l"(a_desc), "l"(b_desc), "r"(idesc), "r"(z), "r"(en)
        : "memory");
}
#define LDTM_X32(r, a) \
    asm volatile( \
        "tcgen05.ld.sync.aligned.32x32b.x32.b32 " \
        "{%0, %1, %2, %3, %4, %5, %6, %7, " \
        " %8, %9, %10, %11, %12, %13, %14, %15, " \
        " %16, %17, %18, %19, %20, %21, %22, %23, " \
        " %24, %25, %26, %27, %28, %29, %30, %31}, [%32];" \
        : "=r"((r)[0]),  "=r"((r)[1]),  "=r"((r)[2]),  "=r"((r)[3]), \
          "=r"((r)[4]),  "=r"((r)[5]),  "=r"((r)[6]),  "=r"((r)[7]), \
          "=r"((r)[8]),  "=r"((r)[9]),  "=r"((r)[10]), "=r"((r)[11]), \
          "=r"((r)[12]), "=r"((r)[13]), "=r"((r)[14]), "=r"((r)[15]), \
          "=r"((r)[16]), "=r"((r)[17]), "=r"((r)[18]), "=r"((r)[19]), \
          "=r"((r)[20]), "=r"((r)[21]), "=r"((r)[22]), "=r"((r)[23]), \
          "=r"((r)[24]), "=r"((r)[25]), "=r"((r)[26]), "=r"((r)[27]), \
          "=r"((r)[28]), "=r"((r)[29]), "=r"((r)[30]), "=r"((r)[31]) \
        : "r"(a))
#endif // HAS_TC

__global__ void __launch_bounds__(256, 2) k_gemm_tc(const int* __restrict__ batch) {
#if HAS_TC
    extern __shared__ char sm[];
    const uint32_t smb = smem_u32(sm);
    const int tid = threadIdx.x;
    const int lane = tid & 31, wid = tid >> 5;
    const int nt = blockIdx.x;                 // icol tile (0..3)
    const int rt = blockIdx.y;                 // 128-row tile (0..1023)
    const int n0 = nt * 256;
    const int row0 = rt * 128;
    int* s_bat = (int*)(sm + 1024);            // 128 ints

    // mbar layout: full[s] @ smb+8+s*8 (s<2), empty[s] @ smb+24+s*8
    if (wid == 0) {
        asm volatile("tcgen05.alloc.cta_group::1.sync.aligned.shared::cta.b32 [%0], %1;"
                     :: "r"(smb), "r"(256) : "memory");
        asm volatile("tcgen05.relinquish_alloc_permit.cta_group::1.sync.aligned;");
    }
    if (tid == 0) {
#pragma unroll
        for (int s = 0; s < 2; s++) {
            MBARRIER_INIT(smb + 8 + s * 8, 1);
            MBARRIER_INIT(smb + 24 + s * 8, 1);
        }
    }
    if (tid < 128) s_bat[tid] = __ldg(&batch[row0 + tid]);
    __syncthreads();
    uint32_t tmem;
    asm volatile("ld.shared.b32 %0, [%1];" : "=r"(tmem) : "r"(smb));

    if (wid == 0) {
        // A: 16 KB half-block of row-tile rt: base (rt/2 * 8 + c)*32768 + (rt&1)*16384
        const char* Abase = (const char*)g_x    + (size_t)(rt >> 1) * 8 * 32768
                                                + (size_t)(rt & 1) * 16384;
        const char* Bbase = (const char*)g_wcat + (size_t)nt * 8 * 32768;
        const uint32_t ep = elect_one_pred();

        auto issue_load = [&](int c, int s) {
            const uint32_t stg = smb + SM_CTRL + s * STG_BYTES;
            const uint32_t fm = smb + 8 + s * 8;
            MBAR_EXPECT_TX(fm, 49152u);
            BULK_CP(stg,          Abase + (size_t)c * 32768, 16384u, fm);
            BULK_CP(stg + 16384u, Bbase + (size_t)c * 32768, 32768u, fm);
        };

        if (ep) { issue_load(0, 0); issue_load(1, 1); }

        for (int c = 0; c < 8; c++) {
            const int s = c & 1;
            const int ph = (c >> 1) & 1;
            MBAR_WAIT(smb + 8 + s * 8, ph);        // stage data ready
            if (ep) {
                const uint32_t stg = smb + SM_CTRL + s * STG_BYTES;
                uint64_t dA = MAKE_SMEM_DESC(stg);
                uint64_t dB = MAKE_SMEM_DESC(stg + 16384u);
#pragma unroll
                for (int ks = 0; ks < 4; ks++) {
                    uint32_t en = (c > 0 || ks > 0) ? 1u : 0u;
                    mma_f16_ss(tmem, dA + ks * 2, dB + ks * 2, IDESC, en);
                }
                asm volatile("tcgen05.commit.cta_group::1.mbarrier::arrive::one.shared::cluster.b64 [%0];"
                             :: "r"(smb + 24 + s * 8) : "memory");
            }
            if (c + 2 < 8) {
                MBAR_WAIT(smb + 24 + s * 8, ph);   // MMA(c) done with stage s
                if (ep) issue_load(c + 2, s);
            }
        }
        // final: 4th commit on each stage (parity 1)
        MBAR_WAIT(smb + 24 + 0 * 8, 1);            // c=6
        MBAR_WAIT(smb + 24 + 1 * 8, 1);            // c=7
    }
    __syncthreads();
    asm volatile("tcgen05.fence::after_thread_sync;" ::: "memory");

    // ---- fused epilogue: two warpgroups on disjoint 64-feature halves ----
    const int wg = wid >> 2;                       // warpgroup 0/1
    const int wg_tid = tid & 127;
    float* s_num = (float*)(sm + SM_CTRL) + wg * (128 * 33 * 2);
    float* s_den = s_num + 128 * 33;
    const int rloc = (wid & 3) * 32 + lane;        // row within 128
    const int dscan = wg_tid & 31, gscan = wg_tid >> 5;

#pragma unroll 1
    for (int p = 0; p < 2; p++) {                  // 2 passes x 32 features per wg
        const int f0 = wg * 64 + p * 32;
        uint32_t rr[64];
        LDTM_X32(rr,      tmem + 2 * f0);
        LDTM_X32(rr + 32, tmem + 2 * f0 + 32);
        asm volatile("tcgen05.wait::ld.sync.aligned;" ::: "memory");
#pragma unroll
        for (int i = 0; i < 32; i++) {
            float y = __uint_as_float(rr[2 * i])     + __ldg(&g_bcat[n0 + 2 * (f0 + i)]);
            float z = __uint_as_float(rr[2 * i + 1]) + __ldg(&g_bcat[n0 + 2 * (f0 + i) + 1]);
            float w = __expf(z);
            s_num[rloc * 33 + i] = w * y;
            s_den[rloc * 33 + i] = w;
        }
        __syncthreads();
        {
            int dglob = (n0 >> 1) + f0 + dscan;
            float an = 0.f, ad = 0.f;
            int curb = s_bat[gscan * 32];
#pragma unroll 4
            for (int r = 0; r < 32; r++) {
                int rr2 = gscan * 32 + r;
                int bb = s_bat[rr2];
                if (bb != curb) {
                    atomicAdd(&g_num[curb * CDIM + dglob], an);
                    atomicAdd(&g_den[curb * CDIM + dglob], ad);
                    an = 0.f; ad = 0.f; curb = bb;
                }
                an += s_num[rr2 * 33 + dscan];
                ad += s_den[rr2 * 33 + dscan];
            }
            atomicAdd(&g_num[curb * CDIM + dglob], an);
            atomicAdd(&g_den[curb * CDIM + dglob], ad);
        }
        __syncthreads();
    }
    if (wid == 0)
        asm volatile("tcgen05.dealloc.cta_group::1.sync.aligned.b32 %0, %1;" :: "r"(tmem), "r"(256));
#endif // HAS_TC
}

// ---------------- K4: finalize out = num / den ----------------
__global__ void k_final(float* __restrict__ out) {
    int i = blockIdx.x * 512 + threadIdx.x;
    float den = g_den[i];
    out[i] = (den > 0.f) ? (g_num[i] / den) : 0.f;
}

// ---------------- host launcher ----------------
extern "C" void kernel_launch(void* const* d_in, const int* in_sizes, int n_in,
                              void* d_out, int out_size) {
    const float* hs    = (const float*)d_in[0];
    const int*   batch = (const int*)d_in[1];
    // d_in[2] = max_nodes (unused)
    const float* gamma = (const float*)d_in[3];
    const float* beta  = (const float*)d_in[4];
    const float* W1    = (const float*)d_in[5];
    const float* b1    = (const float*)d_in[6];
    const float* W2    = (const float*)d_in[7];
    const float* b2    = (const float*)d_in[8];
    float* out = (float*)d_out;

    cudaFuncSetAttribute(k_gemm_tc, cudaFuncAttributeMaxDynamicSharedMemorySize, SM_TOTAL_TC);

    k_wcopy<<<1024, 256>>>(W1);
    k_bcat<<<64, 256>>>(W2, b1, b2);
    dim3 wg(8, 8);
    k_w21<<<wg, 256>>>(W2, W1);
    k_ln<<<16384, 256>>>(hs, gamma, beta);
    dim3 gtc(4, 1024);
    k_gemm_tc<<<gtc, 256, SM_TOTAL_TC>>>(batch);
    k_final<<<128, 512>>>(out);
}

// round 15
// speedup vs baseline: 1.1602x; 1.1602x over previous
#include <cuda_runtime.h>
#include <cuda_fp16.h>
#include <cstdint>
#include <cstddef>

// Problem constants (fixed by dataset)
#define T_TOT 131072
#define CDIM  512
#define NF    1024   // interleaved [y_0,z_0,y_1,z_1,...]  (y=W1 path, z=W2W1 path)
#define BATCH 128

// tcgen05 requires the sm_103a ("arch-accelerated") target pass.
#if defined(__CUDA_ARCH_FEAT_SM103_ALL)
#define HAS_TC 1
#else
#define HAS_TC 0
#endif

// ---------------- scratch: __device__ globals (no allocation allowed) ----------------
// Tiled + pre-swizzled layouts (32 KB blocks = smem images for cp.async.bulk):
// A block (row-tile R of 256 rows, K-chunk c): base=(R*8+c)*32768, two 16 KB
//   sub-halves of 128 rows each -> a 128-row CTA uses one 16 KB half directly.
// B block (icol-tile nt of 256, K-chunk c): base=(nt*8+c)*32768.
__device__ __half g_x[(size_t)T_TOT * CDIM];     // LN output fp16, tiled    134 MB
__device__ __half g_wcat[(size_t)NF * CDIM];     // interleaved weights, tiled (1 MB)
__device__ float  g_bcat[NF];                    // interleaved [b1_d ; (W2 b1 + b2)_d]
__device__ float  g_num[BATCH * CDIM];           // Σ w*y per (graph, d)
__device__ float  g_den[BATCH * CDIM];           // Σ w   per (graph, d)

// ---------------- PTX helpers ----------------
__device__ __forceinline__ uint32_t smem_u32(const void* p) {
    return (uint32_t)__cvta_generic_to_shared(p);
}
#define SWZ128(o) ((o) ^ (((o) >> 3) & 0x70))

// ---------------- K1a: W1 row d -> wcat icol 2d (fp16, tiled); zero accumulators ----
__global__ void k_wcopy(const float* __restrict__ W1) {
    int i = blockIdx.x * 256 + threadIdx.x;      // 262144 elements
    int d = i >> 9, k = i & 511;
    int icol = 2 * d;
    int nt = icol >> 8, rloc = icol & 255;
    int c = k >> 6, klocb = (k & 63) * 2;
    size_t base = ((size_t)(nt * 8 + c)) * 32768;
    uint32_t off = SWZ128((uint32_t)(rloc * 128 + klocb));
    *(__half*)((char*)g_wcat + base + off) = __float2half(W1[i]);
    if (i < BATCH * CDIM) { g_num[i] = 0.f; g_den[i] = 0.f; }
}

// ---------------- K1b: bcat interleaved [b1_d ; (W2@b1+b2)_d], warp-per-output ------
__global__ void k_bcat(const float* __restrict__ W2, const float* __restrict__ b1,
                       const float* __restrict__ b2) {
    int w = (blockIdx.x * 256 + threadIdx.x) >> 5;   // 0..511 (grid 64 x 256)
    int lane = threadIdx.x & 31;
    float acc = 0.f;
    const float* row = W2 + (size_t)w * CDIM;
#pragma unroll 4
    for (int j = lane; j < CDIM; j += 32) acc += row[j] * __ldg(&b1[j]);
#pragma unroll
    for (int o = 16; o > 0; o >>= 1) acc += __shfl_xor_sync(0xFFFFFFFFu, acc, o);
    if (lane == 0) {
        g_bcat[2 * w]     = __ldg(&b1[w]);
        g_bcat[2 * w + 1] = acc + __ldg(&b2[w]);
    }
}

// ---------------- K1c: W21 = W2 @ W1 -> wcat icol 2d+1 (fp16, tiled) ----------------
__global__ void __launch_bounds__(256) k_w21(const float* __restrict__ W2,
                                             const float* __restrict__ W1) {
    __shared__ float sA[32][65];
    __shared__ float sB[32][64];
    int t = threadIdx.x;
    int tx = t & 15, ty = t >> 4;
    int d0 = blockIdx.y * 64, k0 = blockIdx.x * 64;
    float acc[4][4] = {};
    for (int jc = 0; jc < CDIM; jc += 32) {
        for (int i = t; i < 64 * 32; i += 256) {
            int r = i >> 5, j = i & 31;
            sA[j][r] = W2[(size_t)(d0 + r) * CDIM + jc + j];
        }
        for (int i = t; i < 32 * 64; i += 256) {
            int j = i >> 6, c = i & 63;
            sB[j][c] = W1[(size_t)(jc + j) * CDIM + k0 + c];
        }
        __syncthreads();
#pragma unroll
        for (int j = 0; j < 32; j++) {
            float a[4], b[4];
#pragma unroll
            for (int i = 0; i < 4; i++) a[i] = sA[j][ty * 4 + i];
#pragma unroll
            for (int l = 0; l < 4; l++) b[l] = sB[j][tx * 4 + l];
#pragma unroll
            for (int i = 0; i < 4; i++)
#pragma unroll
                for (int l = 0; l < 4; l++) acc[i][l] += a[i] * b[l];
        }
        __syncthreads();
    }
#pragma unroll
    for (int i = 0; i < 4; i++)
#pragma unroll
        for (int l = 0; l < 4; l++) {
            int dr = d0 + ty * 4 + i;
            int k  = k0 + tx * 4 + l;
            int icol = 2 * dr + 1;
            int nt = icol >> 8, rloc = icol & 255;
            int c = k >> 6, klocb = (k & 63) * 2;
            size_t base = ((size_t)(nt * 8 + c)) * 32768;
            uint32_t off = SWZ128((uint32_t)(rloc * 128 + klocb));
            *(__half*)((char*)g_wcat + base + off) = __float2half(acc[i][l]);
        }
}

// ---------------- K2: LayerNorm (eps=1e-5), WARP-PER-ROW, COALESCED ----------------
// 256 threads = 8 rows/block; load i: lane reads float4 #(i*32+lane) -> each
// load is 512 contiguous bytes across the warp. Pure-shfl reduction, no smem.
__global__ void __launch_bounds__(256) k_ln(const float* __restrict__ hs,
                                            const float* __restrict__ gamma,
                                            const float* __restrict__ beta) {
    const int wid = threadIdx.x >> 5;
    const int lane = threadIdx.x & 31;
    const int row = blockIdx.x * 8 + wid;
    const float4* src = (const float4*)(hs + (size_t)row * CDIM);
    float4 v[4];
#pragma unroll
    for (int i = 0; i < 4; i++) v[i] = __ldg(src + i * 32 + lane);
    float s = 0.f, q = 0.f;
#pragma unroll
    for (int i = 0; i < 4; i++) {
        s += v[i].x + v[i].y + v[i].z + v[i].w;
        q += v[i].x * v[i].x + v[i].y * v[i].y + v[i].z * v[i].z + v[i].w * v[i].w;
    }
#pragma unroll
    for (int o = 16; o > 0; o >>= 1) {
        s += __shfl_xor_sync(0xFFFFFFFFu, s, o);
        q += __shfl_xor_sync(0xFFFFFFFFu, q, o);
    }
    const float mu = s * (1.f / CDIM);
    const float var = q * (1.f / CDIM) - mu * mu;
    const float rs = rsqrtf(var + 1e-5f);
    const int R = row >> 8, sub = (row >> 7) & 1, rloc = row & 127;
#pragma unroll
    for (int i = 0; i < 4; i++) {
        float4 g = __ldg((const float4*)gamma + i * 32 + lane);
        float4 b = __ldg((const float4*)beta  + i * 32 + lane);
        __half2 h0 = __floats2half2_rn((v[i].x - mu) * rs * g.x + b.x,
                                       (v[i].y - mu) * rs * g.y + b.y);
        __half2 h1 = __floats2half2_rn((v[i].z - mu) * rs * g.z + b.z,
                                       (v[i].w - mu) * rs * g.w + b.w);
        uint2 packed;
        packed.x = *(uint32_t*)&h0;
        packed.y = *(uint32_t*)&h1;
        const int k = (i * 32 + lane) * 4;         // first col of this 4-col group
        const int c = k >> 6;
        const int klocb = (k & 63) * 2;            // 8-byte aligned
        size_t base = ((size_t)(R * 8 + c)) * 32768 + (size_t)sub * 16384;
        uint32_t off = SWZ128((uint32_t)(rloc * 128 + klocb));
        *(uint2*)((char*)g_x + base + off) = packed;
    }
}

// ============================================================================
// K3: tcgen05 GEMM + fused softmax-pool epilogue (sm_103a pass only)
// CTA tile M=128 x N=256 icols; grid (4 nt, 1024 Rt128); TMEM 256 cols/CTA,
// 2 CTAs/SM. 2-stage bulk-copy pipeline (warp 0), mbarrier full/empty.
// [verbatim from the 303.3 us R7 kernel]
// ============================================================================
#define STG_BYTES 49152           // A 16K | B 32K
#define SM_CTRL   2048
#define SM_TOTAL_TC (SM_CTRL + 2 * STG_BYTES)   // 100352
#define IDESC 0x8400010u          // f16*f16->f32, M=128, N=256

#if HAS_TC
__device__ __forceinline__ uint32_t elect_one_pred() {
    uint32_t pred;
    asm volatile("{\n\t.reg .pred p;\n\telect.sync _|p, 0xFFFFFFFF;\n\tselp.b32 %0, 1, 0, p;\n\t}"
                 : "=r"(pred));
    return pred;
}
static constexpr uint64_t SMEM_DESC_BASE_SW128 =
    (uint64_t(2) << 61) | (uint64_t(1) << 46) | (uint64_t(64) << 32) | (uint64_t(1) << 16);
#define MAKE_SMEM_DESC(b) (SMEM_DESC_BASE_SW128 | ((uint64_t)((b) >> 4) & 0x3FFF))
#define MBARRIER_INIT(a, c) \
    asm volatile("mbarrier.init.shared.b64 [%0], %1;" :: "r"(a), "r"(c) : "memory")
#define MBAR_EXPECT_TX(a, n) \
    asm volatile("mbarrier.arrive.expect_tx.shared.b64 _, [%0], %1;" :: "r"(a), "r"(n) : "memory")
#define MBAR_WAIT(a, ph) do {                                                  \
    asm volatile("{\n\t.reg .pred P1;\n\t"                                     \
        "WL_%=:\n\t"                                                           \
        "mbarrier.try_wait.parity.acquire.cta.shared::cta.b64 P1, [%0], %1, 0x989680;\n\t" \
        "@P1 bra.uni WD_%=;\n\t"                                               \
        "bra.uni WL_%=;\n\t"                                                   \
        "WD_%=:\n\t}" :: "r"(a), "r"(ph) : "memory");                          \
} while (0)
#define BULK_CP(dst, src, n, mbar) \
    asm volatile("cp.async.bulk.shared::cta.global.mbarrier::complete_tx::bytes " \
                 "[%0], [%1], %2, [%3];" \
                 :: "r"(dst), "l"(src), "r"(n), "r"(mbar) : "memory")
__device__ __forceinline__ void mma_f16_ss(uint32_t d_tmem, uint64_t a_desc, uint64_t b_desc,
                                           uint32_t idesc, uint32_t en) {
    uint32_t z = 0;
    asm volatile(
        "{\n\t.reg .pred p;\n\t"
        "setp.ne.u32 p, %5, 0;\n\t"
        "tcgen05.mma.cta_group::1.kind::f16 [%0], %1, %2, %3, {%4, %4, %4, %4}, p;\n\t"
        "}"
        :: "r"(d_tmem), "l"(a_desc), "l"(b_desc), "r"(idesc), "r"(z), "r"(en)
        : "memory");
}
#define LDTM_X32(r, a) \
    asm volatile( \
        "tcgen05.ld.sync.aligned.32x32b.x32.b32 " \
        "{%0, %1, %2, %3, %4, %5, %6, %7, " \
        " %8, %9, %10, %11, %12, %13, %14, %15, " \
        " %16, %17, %18, %19, %20, %21, %22, %23, " \
        " %24, %25, %26, %27, %28, %29, %30, %31}, [%32];" \
        : "=r"((r)[0]),  "=r"((r)[1]),  "=r"((r)[2]),  "=r"((r)[3]), \
          "=r"((r)[4]),  "=r"((r)[5]),  "=r"((r)[6]),  "=r"((r)[7]), \
          "=r"((r)[8]),  "=r"((r)[9]),  "=r"((r)[10]), "=r"((r)[11]), \
          "=r"((r)[12]), "=r"((r)[13]), "=r"((r)[14]), "=r"((r)[15]), \
          "=r"((r)[16]), "=r"((r)[17]), "=r"((r)[18]), "=r"((r)[19]), \
          "=r"((r)[20]), "=r"((r)[21]), "=r"((r)[22]), "=r"((r)[23]), \
          "=r"((r)[24]), "=r"((r)[25]), "=r"((r)[26]), "=r"((r)[27]), \
          "=r"((r)[28]), "=r"((r)[29]), "=r"((r)[30]), "=r"((r)[31]) \
        : "r"(a))
#endif // HAS_TC

__global__ void __launch_bounds__(256, 2) k_gemm_tc(const int* __restrict__ batch) {
#if HAS_TC
    extern __shared__ char sm[];
    const uint32_t smb = smem_u32(sm);
    const int tid = threadIdx.x;
    const int lane = tid & 31, wid = tid >> 5;
    const int nt = blockIdx.x;                 // icol tile (0..3)
    const int rt = blockIdx.y;                 // 128-row tile (0..1023)
    const int n0 = nt * 256;
    const int row0 = rt * 128;
    int* s_bat = (int*)(sm + 1024);            // 128 ints

    // mbar layout: full[s] @ smb+8+s*8 (s<2), empty[s] @ smb+24+s*8
    if (wid == 0) {
        asm volatile("tcgen05.alloc.cta_group::1.sync.aligned.shared::cta.b32 [%0], %1;"
                     :: "r"(smb), "r"(256) : "memory");
        asm volatile("tcgen05.relinquish_alloc_permit.cta_group::1.sync.aligned;");
    }
    if (tid == 0) {
#pragma unroll
        for (int s = 0; s < 2; s++) {
            MBARRIER_INIT(smb + 8 + s * 8, 1);
            MBARRIER_INIT(smb + 24 + s * 8, 1);
        }
    }
    if (tid < 128) s_bat[tid] = __ldg(&batch[row0 + tid]);
    __syncthreads();
    uint32_t tmem;
    asm volatile("ld.shared.b32 %0, [%1];" : "=r"(tmem) : "r"(smb));

    if (wid == 0) {
        // A: 16 KB half-block of row-tile rt: base (rt/2 * 8 + c)*32768 + (rt&1)*16384
        const char* Abase = (const char*)g_x    + (size_t)(rt >> 1) * 8 * 32768
                                                + (size_t)(rt & 1) * 16384;
        const char* Bbase = (const char*)g_wcat + (size_t)nt * 8 * 32768;
        const uint32_t ep = elect_one_pred();

        auto issue_load = [&](int c, int s) {
            const uint32_t stg = smb + SM_CTRL + s * STG_BYTES;
            const uint32_t fm = smb + 8 + s * 8;
            MBAR_EXPECT_TX(fm, 49152u);
            BULK_CP(stg,          Abase + (size_t)c * 32768, 16384u, fm);
            BULK_CP(stg + 16384u, Bbase + (size_t)c * 32768, 32768u, fm);
        };

        if (ep) { issue_load(0, 0); issue_load(1, 1); }

        for (int c = 0; c < 8; c++) {
            const int s = c & 1;
            const int ph = (c >> 1) & 1;
            MBAR_WAIT(smb + 8 + s * 8, ph);        // stage data ready
            if (ep) {
                const uint32_t stg = smb + SM_CTRL + s * STG_BYTES;
                uint64_t dA = MAKE_SMEM_DESC(stg);
                uint64_t dB = MAKE_SMEM_DESC(stg + 16384u);
#pragma unroll
                for (int ks = 0; ks < 4; ks++) {
                    uint32_t en = (c > 0 || ks > 0) ? 1u : 0u;
                    mma_f16_ss(tmem, dA + ks * 2, dB + ks * 2, IDESC, en);
                }
                asm volatile("tcgen05.commit.cta_group::1.mbarrier::arrive::one.shared::cluster.b64 [%0];"
                             :: "r"(smb + 24 + s * 8) : "memory");
            }
            if (c + 2 < 8) {
                MBAR_WAIT(smb + 24 + s * 8, ph);   // MMA(c) done with stage s
                if (ep) issue_load(c + 2, s);
            }
        }
        // final: 4th commit on each stage (parity 1)
        MBAR_WAIT(smb + 24 + 0 * 8, 1);            // c=6
        MBAR_WAIT(smb + 24 + 1 * 8, 1);            // c=7
    }
    __syncthreads();
    asm volatile("tcgen05.fence::after_thread_sync;" ::: "memory");

    // ---- fused epilogue: two warpgroups on disjoint 64-feature halves ----
    const int wg = wid >> 2;                       // warpgroup 0/1
    const int wg_tid = tid & 127;
    float* s_num = (float*)(sm + SM_CTRL) + wg * (128 * 33 * 2);
    float* s_den = s_num + 128 * 33;
    const int rloc = (wid & 3) * 32 + lane;        // row within 128
    const int dscan = wg_tid & 31, gscan = wg_tid >> 5;

#pragma unroll 1
    for (int p = 0; p < 2; p++) {                  // 2 passes x 32 features per wg
        const int f0 = wg * 64 + p * 32;
        uint32_t rr[64];
        LDTM_X32(rr,      tmem + 2 * f0);
        LDTM_X32(rr + 32, tmem + 2 * f0 + 32);
        asm volatile("tcgen05.wait::ld.sync.aligned;" ::: "memory");
#pragma unroll
        for (int i = 0; i < 32; i++) {
            float y = __uint_as_float(rr[2 * i])     + __ldg(&g_bcat[n0 + 2 * (f0 + i)]);
            float z = __uint_as_float(rr[2 * i + 1]) + __ldg(&g_bcat[n0 + 2 * (f0 + i) + 1]);
            float w = __expf(z);
            s_num[rloc * 33 + i] = w * y;
            s_den[rloc * 33 + i] = w;
        }
        __syncthreads();
        {
            int dglob = (n0 >> 1) + f0 + dscan;
            float an = 0.f, ad = 0.f;
            int curb = s_bat[gscan * 32];
#pragma unroll 4
            for (int r = 0; r < 32; r++) {
                int rr2 = gscan * 32 + r;
                int bb = s_bat[rr2];
                if (bb != curb) {
                    atomicAdd(&g_num[curb * CDIM + dglob], an);
                    atomicAdd(&g_den[curb * CDIM + dglob], ad);
                    an = 0.f; ad = 0.f; curb = bb;
                }
                an += s_num[rr2 * 33 + dscan];
                ad += s_den[rr2 * 33 + dscan];
            }
            atomicAdd(&g_num[curb * CDIM + dglob], an);
            atomicAdd(&g_den[curb * CDIM + dglob], ad);
        }
        __syncthreads();
    }
    if (wid == 0)
        asm volatile("tcgen05.dealloc.cta_group::1.sync.aligned.b32 %0, %1;" :: "r"(tmem), "r"(256));
#endif // HAS_TC
}

// ---------------- K4: finalize out = num / den ----------------
__global__ void k_final(float* __restrict__ out) {
    int i = blockIdx.x * 512 + threadIdx.x;
    float den = g_den[i];
    out[i] = (den > 0.f) ? (g_num[i] / den) : 0.f;
}

// ---------------- host launcher ----------------
extern "C" void kernel_launch(void* const* d_in, const int* in_sizes, int n_in,
                              void* d_out, int out_size) {
    const float* hs    = (const float*)d_in[0];
    const int*   batch = (const int*)d_in[1];
    // d_in[2] = max_nodes (unused)
    const float* gamma = (const float*)d_in[3];
    const float* beta  = (const float*)d_in[4];
    const float* W1    = (const float*)d_in[5];
    const float* b1    = (const float*)d_in[6];
    const float* W2    = (const float*)d_in[7];
    const float* b2    = (const float*)d_in[8];
    float* out = (float*)d_out;

    cudaFuncSetAttribute(k_gemm_tc, cudaFuncAttributeMaxDynamicSharedMemorySize, SM_TOTAL_TC);

    k_wcopy<<<1024, 256>>>(W1);
    k_bcat<<<64, 256>>>(W2, b1, b2);
    dim3 wg(8, 8);
    k_w21<<<wg, 256>>>(W2, W1);
    k_ln<<<16384, 256>>>(hs, gamma, beta);
    dim3 gtc(4, 1024);
    k_gemm_tc<<<gtc, 256, SM_TOTAL_TC>>>(batch);
    k_final<<<128, 512>>>(out);
}

// round 16
// speedup vs baseline: 1.1774x; 1.0148x over previous
#include <cuda_runtime.h>
#include <cuda_fp16.h>
#include <cstdint>
#include <cstddef>

// Problem constants (fixed by dataset)
#define T_TOT 131072
#define CDIM  512
#define NF    1024   // interleaved [y_0,z_0,y_1,z_1,...]  (y=W1 path, z=W2W1 path)
#define BATCH 128

// tcgen05 requires the sm_103a ("arch-accelerated") target pass.
#if defined(__CUDA_ARCH_FEAT_SM103_ALL)
#define HAS_TC 1
#else
#define HAS_TC 0
#endif

// ---------------- scratch: __device__ globals (no allocation allowed) ----------------
__device__ __half g_x[(size_t)T_TOT * CDIM];     // LN output fp16, tiled    134 MB
__device__ __half g_wcat[(size_t)NF * CDIM];     // interleaved weights, tiled (1 MB)
__device__ float  g_bcat[NF];                    // interleaved [b1_d ; (W2 b1 + b2)_d]
__device__ float  g_num[BATCH * CDIM];           // Σ w*y per (graph, d)
__device__ float  g_den[BATCH * CDIM];           // Σ w   per (graph, d)
__device__ int    g_smslot[256];                 // per-SM arrival counter (stagger)

// ---------------- PTX helpers ----------------
__device__ __forceinline__ uint32_t smem_u32(const void* p) {
    return (uint32_t)__cvta_generic_to_shared(p);
}
#define SWZ128(o) ((o) ^ (((o) >> 3) & 0x70))

// ---------------- K1a: W1 row d -> wcat icol 2d (fp16, tiled); zero accumulators ----
__global__ void k_wcopy(const float* __restrict__ W1) {
    int i = blockIdx.x * 256 + threadIdx.x;      // 262144 elements
    int d = i >> 9, k = i & 511;
    int icol = 2 * d;
    int nt = icol >> 8, rloc = icol & 255;
    int c = k >> 6, klocb = (k & 63) * 2;
    size_t base = ((size_t)(nt * 8 + c)) * 32768;
    uint32_t off = SWZ128((uint32_t)(rloc * 128 + klocb));
    *(__half*)((char*)g_wcat + base + off) = __float2half(W1[i]);
    if (i < BATCH * CDIM) { g_num[i] = 0.f; g_den[i] = 0.f; }
    if (i < 256) g_smslot[i] = 0;
}

// ---------------- K1b: bcat interleaved [b1_d ; (W2@b1+b2)_d], warp-per-output ------
__global__ void k_bcat(const float* __restrict__ W2, const float* __restrict__ b1,
                       const float* __restrict__ b2) {
    int w = (blockIdx.x * 256 + threadIdx.x) >> 5;   // 0..511 (grid 64 x 256)
    int lane = threadIdx.x & 31;
    float acc = 0.f;
    const float* row = W2 + (size_t)w * CDIM;
#pragma unroll 4
    for (int j = lane; j < CDIM; j += 32) acc += row[j] * __ldg(&b1[j]);
#pragma unroll
    for (int o = 16; o > 0; o >>= 1) acc += __shfl_xor_sync(0xFFFFFFFFu, acc, o);
    if (lane == 0) {
        g_bcat[2 * w]     = __ldg(&b1[w]);
        g_bcat[2 * w + 1] = acc + __ldg(&b2[w]);
    }
}

// ---------------- K1c: W21 = W2 @ W1 -> wcat icol 2d+1 (fp16, tiled) ----------------
__global__ void __launch_bounds__(256) k_w21(const float* __restrict__ W2,
                                             const float* __restrict__ W1) {
    __shared__ float sA[32][65];
    __shared__ float sB[32][64];
    int t = threadIdx.x;
    int tx = t & 15, ty = t >> 4;
    int d0 = blockIdx.y * 64, k0 = blockIdx.x * 64;
    float acc[4][4] = {};
    for (int jc = 0; jc < CDIM; jc += 32) {
        for (int i = t; i < 64 * 32; i += 256) {
            int r = i >> 5, j = i & 31;
            sA[j][r] = W2[(size_t)(d0 + r) * CDIM + jc + j];
        }
        for (int i = t; i < 32 * 64; i += 256) {
            int j = i >> 6, c = i & 63;
            sB[j][c] = W1[(size_t)(jc + j) * CDIM + k0 + c];
        }
        __syncthreads();
#pragma unroll
        for (int j = 0; j < 32; j++) {
            float a[4], b[4];
#pragma unroll
            for (int i = 0; i < 4; i++) a[i] = sA[j][ty * 4 + i];
#pragma unroll
            for (int l = 0; l < 4; l++) b[l] = sB[j][tx * 4 + l];
#pragma unroll
            for (int i = 0; i < 4; i++)
#pragma unroll
                for (int l = 0; l < 4; l++) acc[i][l] += a[i] * b[l];
        }
        __syncthreads();
    }
#pragma unroll
    for (int i = 0; i < 4; i++)
#pragma unroll
        for (int l = 0; l < 4; l++) {
            int dr = d0 + ty * 4 + i;
            int k  = k0 + tx * 4 + l;
            int icol = 2 * dr + 1;
            int nt = icol >> 8, rloc = icol & 255;
            int c = k >> 6, klocb = (k & 63) * 2;
            size_t base = ((size_t)(nt * 8 + c)) * 32768;
            uint32_t off = SWZ128((uint32_t)(rloc * 128 + klocb));
            *(__half*)((char*)g_wcat + base + off) = __float2half(acc[i][l]);
        }
}

// ---------------- K2: LayerNorm (eps=1e-5), WARP-PER-ROW, COALESCED ----------------
__global__ void __launch_bounds__(256) k_ln(const float* __restrict__ hs,
                                            const float* __restrict__ gamma,
                                            const float* __restrict__ beta) {
    const int wid = threadIdx.x >> 5;
    const int lane = threadIdx.x & 31;
    const int row = blockIdx.x * 8 + wid;
    const float4* src = (const float4*)(hs + (size_t)row * CDIM);
    float4 v[4];
#pragma unroll
    for (int i = 0; i < 4; i++) v[i] = __ldg(src + i * 32 + lane);
    float s = 0.f, q = 0.f;
#pragma unroll
    for (int i = 0; i < 4; i++) {
        s += v[i].x + v[i].y + v[i].z + v[i].w;
        q += v[i].x * v[i].x + v[i].y * v[i].y + v[i].z * v[i].z + v[i].w * v[i].w;
    }
#pragma unroll
    for (int o = 16; o > 0; o >>= 1) {
        s += __shfl_xor_sync(0xFFFFFFFFu, s, o);
        q += __shfl_xor_sync(0xFFFFFFFFu, q, o);
    }
    const float mu = s * (1.f / CDIM);
    const float var = q * (1.f / CDIM) - mu * mu;
    const float rs = rsqrtf(var + 1e-5f);
    const int R = row >> 8, sub = (row >> 7) & 1, rloc = row & 127;
#pragma unroll
    for (int i = 0; i < 4; i++) {
        float4 g = __ldg((const float4*)gamma + i * 32 + lane);
        float4 b = __ldg((const float4*)beta  + i * 32 + lane);
        __half2 h0 = __floats2half2_rn((v[i].x - mu) * rs * g.x + b.x,
                                       (v[i].y - mu) * rs * g.y + b.y);
        __half2 h1 = __floats2half2_rn((v[i].z - mu) * rs * g.z + b.z,
                                       (v[i].w - mu) * rs * g.w + b.w);
        uint2 packed;
        packed.x = *(uint32_t*)&h0;
        packed.y = *(uint32_t*)&h1;
        const int k = (i * 32 + lane) * 4;
        const int c = k >> 6;
        const int klocb = (k & 63) * 2;
        size_t base = ((size_t)(R * 8 + c)) * 32768 + (size_t)sub * 16384;
        uint32_t off = SWZ128((uint32_t)(rloc * 128 + klocb));
        *(uint2*)((char*)g_x + base + off) = packed;
    }
}

// ============================================================================
// K3: tcgen05 GEMM + fused softmax-pool epilogue (sm_103a pass only)
// CTA tile M=128 x N=256 icols; grid (4 nt, 1024 Rt128); TMEM 256 cols/CTA,
// 2 CTAs/SM. 2-stage bulk-copy pipeline (warp 0), mbarrier full/empty.
// NEW: one-time per-SM stagger (second arriver delays ~12K cyc) to de-phase
// co-resident CTAs; epilogue barriers relaxed to __syncwarp (scan is warp-local).
// ============================================================================
#define STG_BYTES 49152           // A 16K | B 32K
#define SM_CTRL   2048
#define SM_TOTAL_TC (SM_CTRL + 2 * STG_BYTES)   // 100352
#define IDESC 0x8400010u          // f16*f16->f32, M=128, N=256

#if HAS_TC
__device__ __forceinline__ uint32_t elect_one_pred() {
    uint32_t pred;
    asm volatile("{\n\t.reg .pred p;\n\telect.sync _|p, 0xFFFFFFFF;\n\tselp.b32 %0, 1, 0, p;\n\t}"
                 : "=r"(pred));
    return pred;
}
static constexpr uint64_t SMEM_DESC_BASE_SW128 =
    (uint64_t(2) << 61) | (uint64_t(1) << 46) | (uint64_t(64) << 32) | (uint64_t(1) << 16);
#define MAKE_SMEM_DESC(b) (SMEM_DESC_BASE_SW128 | ((uint64_t)((b) >> 4) & 0x3FFF))
#define MBARRIER_INIT(a, c) \
    asm volatile("mbarrier.init.shared.b64 [%0], %1;" :: "r"(a), "r"(c) : "memory")
#define MBAR_EXPECT_TX(a, n) \
    asm volatile("mbarrier.arrive.expect_tx.shared.b64 _, [%0], %1;" :: "r"(a), "r"(n) : "memory")
#define MBAR_WAIT(a, ph) do {                                                  \
    asm volatile("{\n\t.reg .pred P1;\n\t"                                     \
        "WL_%=:\n\t"                                                           \
        "mbarrier.try_wait.parity.acquire.cta.shared::cta.b64 P1, [%0], %1, 0x989680;\n\t" \
        "@P1 bra.uni WD_%=;\n\t"                                               \
        "bra.uni WL_%=;\n\t"                                                   \
        "WD_%=:\n\t}" :: "r"(a), "r"(ph) : "memory");                          \
} while (0)
#define BULK_CP(dst, src, n, mbar) \
    asm volatile("cp.async.bulk.shared::cta.global.mbarrier::complete_tx::bytes " \
                 "[%0], [%1], %2, [%3];" \
                 :: "r"(dst), "l"(src), "r"(n), "r"(mbar) : "memory")
__device__ __forceinline__ void mma_f16_ss(uint32_t d_tmem, uint64_t a_desc, uint64_t b_desc,
                                           uint32_t idesc, uint32_t en) {
    uint32_t z = 0;
    asm volatile(
        "{\n\t.reg .pred p;\n\t"
        "setp.ne.u32 p, %5, 0;\n\t"
        "tcgen05.mma.cta_group::1.kind::f16 [%0], %1, %2, %3, {%4, %4, %4, %4}, p;\n\t"
        "}"
        :: "r"(d_tmem), "l"(a_desc), "l"(b_desc), "r"(idesc), "r"(z), "r"(en)
        : "memory");
}
#define LDTM_X32(r, a) \
    asm volatile( \
        "tcgen05.ld.sync.aligned.32x32b.x32.b32 " \
        "{%0, %1, %2, %3, %4, %5, %6, %7, " \
        " %8, %9, %10, %11, %12, %13, %14, %15, " \
        " %16, %17, %18, %19, %20, %21, %22, %23, " \
        " %24, %25, %26, %27, %28, %29, %30, %31}, [%32];" \
        : "=r"((r)[0]),  "=r"((r)[1]),  "=r"((r)[2]),  "=r"((r)[3]), \
          "=r"((r)[4]),  "=r"((r)[5]),  "=r"((r)[6]),  "=r"((r)[7]), \
          "=r"((r)[8]),  "=r"((r)[9]),  "=r"((r)[10]), "=r"((r)[11]), \
          "=r"((r)[12]), "=r"((r)[13]), "=r"((r)[14]), "=r"((r)[15]), \
          "=r"((r)[16]), "=r"((r)[17]), "=r"((r)[18]), "=r"((r)[19]), \
          "=r"((r)[20]), "=r"((r)[21]), "=r"((r)[22]), "=r"((r)[23]), \
          "=r"((r)[24]), "=r"((r)[25]), "=r"((r)[26]), "=r"((r)[27]), \
          "=r"((r)[28]), "=r"((r)[29]), "=r"((r)[30]), "=r"((r)[31]) \
        : "r"(a))
#endif // HAS_TC

__global__ void __launch_bounds__(256, 2) k_gemm_tc(const int* __restrict__ batch) {
#if HAS_TC
    extern __shared__ char sm[];
    const uint32_t smb = smem_u32(sm);
    const int tid = threadIdx.x;
    const int lane = tid & 31, wid = tid >> 5;
    const int nt = blockIdx.x;                 // icol tile (0..3)
    const int rt = blockIdx.y;                 // 128-row tile (0..1023)
    const int n0 = nt * 256;
    const int row0 = rt * 128;
    int* s_bat = (int*)(sm + 1024);            // 128 ints

    // mbar layout: full[s] @ smb+8+s*8 (s<2), empty[s] @ smb+24+s*8
    if (wid == 0) {
        asm volatile("tcgen05.alloc.cta_group::1.sync.aligned.shared::cta.b32 [%0], %1;"
                     :: "r"(smb), "r"(256) : "memory");
        asm volatile("tcgen05.relinquish_alloc_permit.cta_group::1.sync.aligned;");
    }
    if (tid == 0) {
#pragma unroll
        for (int s = 0; s < 2; s++) {
            MBARRIER_INIT(smb + 8 + s * 8, 1);
            MBARRIER_INIT(smb + 24 + s * 8, 1);
        }
    }
    if (tid < 128) s_bat[tid] = __ldg(&batch[row0 + tid]);
    __syncthreads();
    uint32_t tmem;
    asm volatile("ld.shared.b32 %0, [%1];" : "=r"(tmem) : "r"(smb));

    if (wid == 0) {
        // ---- one-time de-phasing: 2nd CTA to ever arrive on this SM delays ----
        {
            uint32_t dly = 0;
            if (lane == 0) {
                uint32_t smid;
                asm("mov.u32 %0, %%smid;" : "=r"(smid));
                int old = atomicAdd(&g_smslot[smid & 255], 1);
                dly = (old == 1) ? 1u : 0u;
            }
            dly = __shfl_sync(0xFFFFFFFFu, dly, 0);
            if (dly) {
                long long t0 = clock64();
                while (clock64() - t0 < 12000) { }
            }
        }
        // A: 16 KB half-block of row-tile rt: base (rt/2 * 8 + c)*32768 + (rt&1)*16384
        const char* Abase = (const char*)g_x    + (size_t)(rt >> 1) * 8 * 32768
                                                + (size_t)(rt & 1) * 16384;
        const char* Bbase = (const char*)g_wcat + (size_t)nt * 8 * 32768;
        const uint32_t ep = elect_one_pred();

        auto issue_load = [&](int c, int s) {
            const uint32_t stg = smb + SM_CTRL + s * STG_BYTES;
            const uint32_t fm = smb + 8 + s * 8;
            MBAR_EXPECT_TX(fm, 49152u);
            BULK_CP(stg,          Abase + (size_t)c * 32768, 16384u, fm);
            BULK_CP(stg + 16384u, Bbase + (size_t)c * 32768, 32768u, fm);
        };

        if (ep) { issue_load(0, 0); issue_load(1, 1); }

        for (int c = 0; c < 8; c++) {
            const int s = c & 1;
            const int ph = (c >> 1) & 1;
            MBAR_WAIT(smb + 8 + s * 8, ph);        // stage data ready
            if (ep) {
                const uint32_t stg = smb + SM_CTRL + s * STG_BYTES;
                uint64_t dA = MAKE_SMEM_DESC(stg);
                uint64_t dB = MAKE_SMEM_DESC(stg + 16384u);
#pragma unroll
                for (int ks = 0; ks < 4; ks++) {
                    uint32_t en = (c > 0 || ks > 0) ? 1u : 0u;
                    mma_f16_ss(tmem, dA + ks * 2, dB + ks * 2, IDESC, en);
                }
                asm volatile("tcgen05.commit.cta_group::1.mbarrier::arrive::one.shared::cluster.b64 [%0];"
                             :: "r"(smb + 24 + s * 8) : "memory");
            }
            if (c + 2 < 8) {
                MBAR_WAIT(smb + 24 + s * 8, ph);   // MMA(c) done with stage s
                if (ep) issue_load(c + 2, s);
            }
        }
        // final: 4th commit on each stage (parity 1)
        MBAR_WAIT(smb + 24 + 0 * 8, 1);            // c=6
        MBAR_WAIT(smb + 24 + 1 * 8, 1);            // c=7
    }
    __syncthreads();
    asm volatile("tcgen05.fence::after_thread_sync;" ::: "memory");

    // ---- fused epilogue: two warpgroups on disjoint 64-feature halves.
    // Scan is WARP-LOCAL (warp g writes rows g*32+lane; its scanners read only
    // those rows), so __syncwarp suffices instead of block barriers.
    const int wg = wid >> 2;                       // warpgroup 0/1
    const int wg_tid = tid & 127;
    float* s_num = (float*)(sm + SM_CTRL) + wg * (128 * 33 * 2);
    float* s_den = s_num + 128 * 33;
    const int rloc = (wid & 3) * 32 + lane;        // row within 128
    const int dscan = wg_tid & 31, gscan = wg_tid >> 5;

#pragma unroll 1
    for (int p = 0; p < 2; p++) {                  // 2 passes x 32 features per wg
        const int f0 = wg * 64 + p * 32;
        uint32_t rr[64];
        LDTM_X32(rr,      tmem + 2 * f0);
        LDTM_X32(rr + 32, tmem + 2 * f0 + 32);
        asm volatile("tcgen05.wait::ld.sync.aligned;" ::: "memory");
#pragma unroll
        for (int i = 0; i < 32; i++) {
            float y = __uint_as_float(rr[2 * i])     + __ldg(&g_bcat[n0 + 2 * (f0 + i)]);
            float z = __uint_as_float(rr[2 * i + 1]) + __ldg(&g_bcat[n0 + 2 * (f0 + i) + 1]);
            float w = __expf(z);
            s_num[rloc * 33 + i] = w * y;
            s_den[rloc * 33 + i] = w;
        }
        __syncwarp();
        {
            int dglob = (n0 >> 1) + f0 + dscan;
            float an = 0.f, ad = 0.f;
            int curb = s_bat[gscan * 32];
#pragma unroll 4
            for (int r = 0; r < 32; r++) {
                int rr2 = gscan * 32 + r;
                int bb = s_bat[rr2];
                if (bb != curb) {
                    atomicAdd(&g_num[curb * CDIM + dglob], an);
                    atomicAdd(&g_den[curb * CDIM + dglob], ad);
                    an = 0.f; ad = 0.f; curb = bb;
                }
                an += s_num[rr2 * 33 + dscan];
                ad += s_den[rr2 * 33 + dscan];
            }
            atomicAdd(&g_num[curb * CDIM + dglob], an);
            atomicAdd(&g_den[curb * CDIM + dglob], ad);
        }
        __syncwarp();
    }
    __syncthreads();
    if (wid == 0)
        asm volatile("tcgen05.dealloc.cta_group::1.sync.aligned.b32 %0, %1;" :: "r"(tmem), "r"(256));
#endif // HAS_TC
}

// ---------------- K4: finalize out = num / den ----------------
__global__ void k_final(float* __restrict__ out) {
    int i = blockIdx.x * 512 + threadIdx.x;
    float den = g_den[i];
    out[i] = (den > 0.f) ? (g_num[i] / den) : 0.f;
}

// ---------------- host launcher ----------------
extern "C" void kernel_launch(void* const* d_in, const int* in_sizes, int n_in,
                              void* d_out, int out_size) {
    const float* hs    = (const float*)d_in[0];
    const int*   batch = (const int*)d_in[1];
    // d_in[2] = max_nodes (unused)
    const float* gamma = (const float*)d_in[3];
    const float* beta  = (const float*)d_in[4];
    const float* W1    = (const float*)d_in[5];
    const float* b1    = (const float*)d_in[6];
    const float* W2    = (const float*)d_in[7];
    const float* b2    = (const float*)d_in[8];
    float* out = (float*)d_out;

    cudaFuncSetAttribute(k_gemm_tc, cudaFuncAttributeMaxDynamicSharedMemorySize, SM_TOTAL_TC);

    k_wcopy<<<1024, 256>>>(W1);
    k_bcat<<<64, 256>>>(W2, b1, b2);
    dim3 wg(8, 8);
    k_w21<<<wg, 256>>>(W2, W1);
    k_ln<<<16384, 256>>>(hs, gamma, beta);
    dim3 gtc(4, 1024);
    k_gemm_tc<<<gtc, 256, SM_TOTAL_TC>>>(batch);
    k_final<<<128, 512>>>(out);
}